// round 9
// baseline (speedup 1.0000x reference)
#include <cuda_runtime.h>
#include <math.h>

#define BB 8
#define LL 2048
#define KSEL 64
#define GRP 8            // rows per group == warps per block
#define NGROUPS 4
#define ROWSB (GRP * NGROUPS)     // 32 rows per block
#define NBINS 256
#define THREADS 256
#define NBLK (BB * LL / ROWSB)    // 512
#define BLKPB (LL / ROWSB)        // 64 blocks per batch
#define POOLCAP 4096

// scratch (no cudaMalloc allowed)
__device__ float4 g_spts[BB * LL];          // sorted points (x,y,z,rho)
__device__ unsigned short g_orig[BB * LL];  // original index per sorted slot
__device__ float g_blocksum[NBLK];
__device__ unsigned int g_done = 0;

// dynamic smem: pts 32KB + pool 8KB + hist 8KB + orig 4KB = 52KB
#define SM_PTS_BYTES  (LL * 16)
#define SM_POOL_BYTES (POOLCAP * 2)
#define SM_HIST_BYTES (GRP * NBINS * 4)
#define SM_ORIG_BYTES (LL * 2)
#define SM_DYN_BYTES  (SM_PTS_BYTES + SM_POOL_BYTES + SM_HIST_BYTES + SM_ORIG_BYTES)

typedef unsigned long long u64;

__device__ __forceinline__ u64 pack2(float lo, float hi) {
    u64 r; asm("mov.b64 %0,{%1,%2};" : "=l"(r) : "f"(lo), "f"(hi)); return r;
}
__device__ __forceinline__ u64 add2(u64 a, u64 b) {
    u64 r; asm("add.rn.f32x2 %0,%1,%2;" : "=l"(r) : "l"(a), "l"(b)); return r;
}
__device__ __forceinline__ u64 fma2(u64 a, u64 b, u64 c) {
    u64 r; asm("fma.rn.f32x2 %0,%1,%2,%3;" : "=l"(r) : "l"(a), "l"(b), "l"(c)); return r;
}
__device__ __forceinline__ void unpack2(u64 v, unsigned &lo, unsigned &hi) {
    asm("mov.b64 {%0,%1},%2;" : "=r"(lo), "=r"(hi) : "l"(v));
}

__device__ __forceinline__ float dist2(float4 a, float4 b) {
    float dx = a.x - b.x, dy = a.y - b.y, dz = a.z - b.z;
    return fmaf(dx, dx, fmaf(dy, dy, dz * dz));
}

__device__ __forceinline__ float contrib(float d2, float r0) {
    float r = sqrtf(fmaxf(d2, 1e-12f));
    float x = (r0 - r) * (1.0f / 0.3f);                       // (r0-r)/DELTA
    float sp = fmaxf(x, 0.0f) + log1pf(expf(-fabsf(x)));      // stable softplus
    float t = fminf(fmaxf((r - 8.0f) * 0.5f, 0.0f), 1.0f);    // smooth switch
    float sw = 1.0f - t * t * (3.0f - 2.0f * t);
    return 10.0f * sp * sw;                                   // WALL * sp * sw
}

__device__ __forceinline__ unsigned part5(unsigned v) {
    // spread 5 bits to every 3rd position: b4..b0 -> bits 12,9,6,3,0
    return (v & 1u) | ((v & 2u) << 2) | ((v & 4u) << 4)
         | ((v & 8u) << 6) | ((v & 16u) << 8);
}

// ---------------- per-batch Morton sort (deterministic bitonic) ----------------
__global__ void __launch_bounds__(THREADS)
sort_kernel(const float* __restrict__ R,
            const void*  __restrict__ seq,
            const float* __restrict__ emb,
            const float* __restrict__ wv,
            const float* __restrict__ bp) {
    __shared__ unsigned keys[LL];
    __shared__ float s_dotv[20];
    __shared__ int s_flag64;

    const int b = blockIdx.x;
    const int tid = threadIdx.x;

    if (tid == 0) s_flag64 = 1;
    if (tid < 20) {
        float x = bp[0];
#pragma unroll
        for (int d = 0; d < 16; d++) x = fmaf(emb[tid * 16 + d], wv[d], x);
        s_dotv[tid] = x;
    }
    __syncthreads();
    if (tid < 64 && ((const int*)seq)[2 * tid + 1] != 0) s_flag64 = 0;
    __syncthreads();
    const bool is64 = (s_flag64 != 0);

    const float* Rb = R + (size_t)b * LL * 3;
    for (int j = tid; j < LL; j += THREADS) {
        float x = Rb[j * 3 + 0], y = Rb[j * 3 + 1], z = Rb[j * 3 + 2];
        int cx = (int)((x + 40.0f) * 0.4f); cx = min(max(cx, 0), 31);
        int cy = (int)((y + 40.0f) * 0.4f); cy = min(max(cy, 0), 31);
        int cz = (int)((z + 40.0f) * 0.4f); cz = min(max(cz, 0), 31);
        unsigned m = (part5(cz) << 2) | (part5(cy) << 1) | part5(cx);
        keys[j] = (m << 11) | (unsigned)j;    // unique keys -> deterministic
    }
    __syncthreads();

    // bitonic sort ascending
    for (unsigned k = 2; k <= LL; k <<= 1) {
        for (unsigned s = k >> 1; s > 0; s >>= 1) {
            for (int t = tid; t < LL / 2; t += THREADS) {
                unsigned i = 2u * t - (t & (s - 1));
                unsigned j = i + s;
                bool up = ((i & k) == 0);
                unsigned a = keys[i], c = keys[j];
                if ((a > c) == up) { keys[i] = c; keys[j] = a; }
            }
            __syncthreads();
        }
    }

    for (int p = tid; p < LL; p += THREADS) {
        int orig = (int)(keys[p] & 2047u);
        int s;
        if (is64) s = (int)((const long long*)seq)[(size_t)b * LL + orig];
        else      s = ((const int*)seq)[b * LL + orig];
        float rho = 1.6f + 1.2f / (1.0f + expf(-s_dotv[s]));
        g_spts[b * LL + p] = make_float4(Rb[orig * 3 + 0], Rb[orig * 3 + 1],
                                         Rb[orig * 3 + 2], rho);
        g_orig[b * LL + p] = (unsigned short)orig;
    }
}

// ---------------- main kernel ----------------
__global__ void __launch_bounds__(THREADS, 4)
main_kernel(float* __restrict__ out) {
    extern __shared__ char smem[];
    float4*         s_pts  = (float4*)smem;
    unsigned short* s_pool = (unsigned short*)(smem + SM_PTS_BYTES);
    int*            s_hist = (int*)(smem + SM_PTS_BYTES + SM_POOL_BYTES);
    unsigned short* s_orig = (unsigned short*)(smem + SM_PTS_BYTES + SM_POOL_BYTES + SM_HIST_BYTES);

    __shared__ int   s_tb[GRP], s_mm[GRP], s_bcnt[GRP];
    __shared__ float s_bnd_d2[GRP][64];
    __shared__ unsigned short s_bnd_j[GRP][64];
    __shared__ float s_wsum[GRP];
    __shared__ int   s_last, s_poolcnt;

    const int tid  = threadIdx.x;
    const int lane = tid & 31;
    const int wid  = tid >> 5;
    const int b    = blockIdx.x >> 6;           // 64 blocks per batch
    const int row0 = (blockIdx.x & 63) * ROWSB;

    for (int j = tid; j < LL; j += THREADS) {
        s_pts[j]  = g_spts[b * LL + j];
        s_orig[j] = g_orig[b * LL + j];
    }

    float lsum = 0.0f;
    const u64 C100 = pack2(-100.0f, -100.0f);

    for (int g = 0; g < NGROUPS; g++) {
        const int i0 = row0 + g * GRP;

        __syncthreads();
        if (tid == 0) s_poolcnt = 0;
        if (tid < GRP) s_bcnt[tid] = 0;
#pragma unroll
        for (int k = 0; k < (GRP * NBINS) / THREADS; k++)
            s_hist[k * THREADS + tid] = 0;
        __syncthreads();

        // group centroid + radius (rows are spatially tight after Morton sort)
        float ccx = 0.f, ccy = 0.f, ccz = 0.f;
#pragma unroll
        for (int k = 0; k < GRP; k++) {
            float4 p = s_pts[i0 + k];
            ccx += p.x; ccy += p.y; ccz += p.z;
        }
        ccx *= 0.125f; ccy *= 0.125f; ccz *= 0.125f;
        float a2 = 0.f;
#pragma unroll
        for (int k = 0; k < GRP; k++) {
            float4 p = s_pts[i0 + k];
            float dx = p.x - ccx, dy = p.y - ccy, dz = p.z - ccz;
            a2 = fmaxf(a2, fmaf(dx, dx, fmaf(dy, dy, dz * dz)));
        }
        float thr = 10.0f + sqrtf(a2) + 0.01f;
        float thr2 = thr * thr;

        // negated row broadcasts (packed pairs)
        u64 nx2[4], ny2[4], nz2[4];
#pragma unroll
        for (int rp = 0; rp < 4; rp++) {
            float4 a  = s_pts[i0 + 2 * rp];
            float4 b2 = s_pts[i0 + 2 * rp + 1];
            nx2[rp] = pack2(-a.x, -b2.x);
            ny2[rp] = pack2(-a.y, -b2.y);
            nz2[rp] = pack2(-a.z, -b2.z);
        }

        // ---- pass 1: per-warp tile prune, packed distances, pool append ----
#pragma unroll
        for (int jj = 0; jj < LL / (2 * THREADS); jj++) {
            int j1 = jj * (2 * THREADS) + wid * 64 + lane;   // warp tile: 64 contiguous
            int j2 = j1 + 32;
            float4 p1 = s_pts[j1];
            float4 p2 = s_pts[j2];
            float e1x = p1.x - ccx, e1y = p1.y - ccy, e1z = p1.z - ccz;
            float e2x = p2.x - ccx, e2y = p2.y - ccy, e2z = p2.z - ccz;
            float dc1 = fmaf(e1x, e1x, fmaf(e1y, e1y, e1z * e1z));
            float dc2 = fmaf(e2x, e2x, fmaf(e2y, e2y, e2z * e2z));
            bool anyp = (dc1 < thr2) || (dc2 < thr2);
            if (!__ballot_sync(0xffffffffu, anyp)) continue;  // whole tile far

            u64 p1x = pack2(p1.x, p1.x), p1y = pack2(p1.y, p1.y), p1z = pack2(p1.z, p1.z);
            u64 p2x = pack2(p2.x, p2.x), p2y = pack2(p2.y, p2.y), p2z = pack2(p2.z, p2.z);
            unsigned mask = 0;
#pragma unroll
            for (int rp = 0; rp < 4; rp++) {
                u64 dx = add2(p1x, nx2[rp]);
                u64 dy = add2(p1y, ny2[rp]);
                u64 dz = add2(p1z, nz2[rp]);
                u64 t  = fma2(dz, dz, C100);
                t = fma2(dy, dy, t);
                t = fma2(dx, dx, t);               // d2 - 100 per half
                unsigned lo, hi; unpack2(t, lo, hi);
                mask |= (lo >> 31) << (2 * rp);
                mask |= (hi >> 31) << (2 * rp + 1);

                dx = add2(p2x, nx2[rp]);
                dy = add2(p2y, ny2[rp]);
                dz = add2(p2z, nz2[rp]);
                t  = fma2(dz, dz, C100);
                t = fma2(dy, dy, t);
                t = fma2(dx, dx, t);
                unpack2(t, lo, hi);
                mask |= (lo >> 31) << (8 + 2 * rp);
                mask |= (hi >> 31) << (8 + 2 * rp + 1);
            }
            // NOTE: bonded exclusion deferred to pool passes (orig-index check)

            int cnt = __popc(mask);
            int scan = cnt;
#pragma unroll
            for (int off = 1; off < 32; off <<= 1) {
                int v = __shfl_up_sync(0xffffffffu, scan, off);
                if (lane >= off) scan += v;
            }
            int base = 0;
            if (lane == 31) base = atomicAdd(&s_poolcnt, scan);
            base = __shfl_sync(0xffffffffu, base, 31) + scan - cnt;
            unsigned mm2 = mask;
            while (mm2) {
                int bpos = __ffs(mm2) - 1;
                mm2 &= mm2 - 1;
                int k  = bpos & 7;
                int jx = j1 + ((bpos & 8) << 2);   // +32 if second point
                if (base < POOLCAP)
                    s_pool[base] = (unsigned short)((jx << 3) | k);
                base++;
            }
        }
        __syncthreads();

        int cnt_all = s_poolcnt; if (cnt_all > POOLCAP) cnt_all = POOLCAP;

        // ---- histogram over pool (orig-index exclusion applied here) ----
        for (int e = tid; e < cnt_all; e += THREADS) {
            int rec = s_pool[e];
            int k = rec & 7, j = rec >> 3;
            int diff = (int)s_orig[i0 + k] - (int)s_orig[j];
            if (diff < 0) diff = -diff;
            if (diff > 2) {
                float d2 = dist2(s_pts[i0 + k], s_pts[j]);
                int bin = (int)(d2 * 2.56f); if (bin > 255) bin = 255;
                atomicAdd(&s_hist[k * NBINS + bin], 1);
            }
        }
        __syncthreads();

        // ---- threshold scan: warp w -> row w ----
        {
            int* hist = s_hist + wid * NBINS;
            int loc[8]; int ssum = 0;
#pragma unroll
            for (int k = 0; k < 8; k++) { loc[k] = hist[lane * 8 + k]; ssum += loc[k]; }
            int scan = ssum;
#pragma unroll
            for (int off = 1; off < 32; off <<= 1) {
                int v = __shfl_up_sync(0xffffffffu, scan, off);
                if (lane >= off) scan += v;
            }
            int total  = __shfl_sync(0xffffffffu, scan, 31);
            int before = scan - ssum;
            bool own = (total > KSEL) && (before < KSEL) && (scan >= KSEL);
            int tb = NBINS, mm = 0;
            if (own) {
                int cum = before;
#pragma unroll
                for (int k = 0; k < 8; k++) {
                    if (cum + loc[k] >= KSEL) { tb = lane * 8 + k; mm = KSEL - cum; break; }
                    cum += loc[k];
                }
            }
            unsigned omsk = __ballot_sync(0xffffffffu, own);
            if (omsk) {
                int src = __ffs(omsk) - 1;
                tb = __shfl_sync(0xffffffffu, tb, src);
                mm = __shfl_sync(0xffffffffu, mm, src);
            }
            if (lane == 0) { s_tb[wid] = tb; s_mm[wid] = mm; }
        }
        __syncthreads();

        // ---- accumulate over pool; collect boundary candidates ----
        for (int e = tid; e < cnt_all; e += THREADS) {
            int rec = s_pool[e];
            int k = rec & 7, j = rec >> 3;
            int diff = (int)s_orig[i0 + k] - (int)s_orig[j];
            if (diff < 0) diff = -diff;
            if (diff <= 2) continue;
            float4 pi = s_pts[i0 + k];
            float4 pj = s_pts[j];
            float d2 = dist2(pi, pj);
            int bin = (int)(d2 * 2.56f); if (bin > 255) bin = 255;
            int tb = s_tb[k];
            if (bin < tb) {
                lsum += contrib(d2, pi.w + pj.w);
            } else if (bin == tb) {
                int pos = atomicAdd(&s_bcnt[k], 1);
                if (pos < 64) {
                    s_bnd_d2[k][pos] = d2;
                    s_bnd_j[k][pos] = (unsigned short)j;
                }
            }
        }
        __syncthreads();

        // ---- boundary rank-select: warp w -> row w (tiny) ----
        {
            int bcnt = s_bcnt[wid]; if (bcnt > 64) bcnt = 64;
            int mm = s_mm[wid];
            float riw = s_pts[i0 + wid].w;
            for (int e = lane; e < bcnt; e += 32) {
                float dk = s_bnd_d2[wid][e]; int jk = s_bnd_j[wid][e];
                int rank = 0;
                for (int l = 0; l < bcnt; l++) {
                    float dl = s_bnd_d2[wid][l];
                    rank += (dl < dk) || (dl == dk && s_bnd_j[wid][l] < jk);
                }
                if (rank < mm) lsum += contrib(dk, riw + s_pts[jk].w);
            }
        }
    }

    // ---- deterministic block reduction ----
#pragma unroll
    for (int off = 16; off; off >>= 1) lsum += __shfl_down_sync(0xffffffffu, lsum, off);
    if (lane == 0) s_wsum[wid] = lsum;
    __syncthreads();
    if (tid == 0) {
        float bs = 0.0f;
#pragma unroll
        for (int w2 = 0; w2 < GRP; w2++) bs += s_wsum[w2];
        g_blocksum[blockIdx.x] = bs;
        __threadfence();
        unsigned t = atomicAdd(&g_done, 1u);
        s_last = (t == NBLK - 1);
    }
    __syncthreads();

    // ---- last block: per-batch reduce in fixed order ----
    if (s_last) {
        __threadfence();
        volatile float* vb = g_blocksum;
        float s = vb[wid * BLKPB + lane] + vb[wid * BLKPB + lane + 32];
#pragma unroll
        for (int off = 16; off; off >>= 1) s += __shfl_down_sync(0xffffffffu, s, off);
        if (lane == 0) out[wid] = s;
        __syncthreads();
        if (tid == 0) g_done = 0;    // reset for next graph replay
    }
}

extern "C" void kernel_launch(void* const* d_in, const int* in_sizes, int n_in,
                              void* d_out, int out_size) {
    const float* R   = (const float*)d_in[0];
    const void*  seq = d_in[1];
    const float* emb = (const float*)d_in[2];
    const float* w   = (const float*)d_in[3];
    const float* bp  = (const float*)d_in[4];
    float* out = (float*)d_out;

    static int attr_set = 0;
    if (!attr_set) {
        cudaFuncSetAttribute(main_kernel,
                             cudaFuncAttributeMaxDynamicSharedMemorySize,
                             SM_DYN_BYTES);
        attr_set = 1;
    }
    sort_kernel<<<BB, THREADS>>>(R, seq, emb, w, bp);
    main_kernel<<<NBLK, THREADS, SM_DYN_BYTES>>>(out);
}